// round 6
// baseline (speedup 1.0000x reference)
#include <cuda_runtime.h>
#include <cstdint>

static constexpr int BATCH   = 20000;
static constexpr int A_BYTES = 131072;   // 8 K-chunks x 128 rows x 128B tf32 W tile
static constexpr int GRID    = 152;      // one persistent CTA per SM
static constexpr int SMEM_BYTES = A_BYTES + 2 * 224 * 128;   // max NT = 224

__device__ __forceinline__ uint32_t smem_u32(const void* p) {
    uint32_t a;
    asm("{ .reg .u64 t; cvta.to.shared.u64 t, %1; cvt.u32.u64 %0, t; }" : "=r"(a) : "l"(p));
    return a;
}
__device__ __forceinline__ uint32_t f2tf32(float f) {
    uint32_t u;
    asm("cvt.rna.tf32.f32 %0, %1;" : "=r"(u) : "f"(f));
    return u;
}
__device__ __forceinline__ uint32_t sw128(uint32_t o) { return o ^ ((o >> 3) & 0x70); }

__device__ __forceinline__ void ldsm4(uint32_t* r, uint32_t a) {
    asm volatile("ldmatrix.sync.aligned.m8n8.x4.shared.b16 {%0,%1,%2,%3}, [%4];"
                 : "=r"(r[0]), "=r"(r[1]), "=r"(r[2]), "=r"(r[3]) : "r"(a));
}
__device__ __forceinline__ void ldsm2(uint32_t* r, uint32_t a) {
    asm volatile("ldmatrix.sync.aligned.m8n8.x2.shared.b16 {%0,%1}, [%2];"
                 : "=r"(r[0]), "=r"(r[1]) : "r"(a));
}
__device__ __forceinline__ void mma8(float* c, const uint32_t* a, const uint32_t* b) {
    asm volatile("mma.sync.aligned.m16n8k8.row.col.f32.tf32.tf32.f32 "
                 "{%0,%1,%2,%3}, {%4,%5,%6,%7}, {%8,%9}, {%0,%1,%2,%3};"
                 : "+f"(c[0]), "+f"(c[1]), "+f"(c[2]), "+f"(c[3])
                 : "r"(a[0]), "r"(a[1]), "r"(a[2]), "r"(a[3]), "r"(b[0]), "r"(b[1]));
}

// Per l: Y[o, n] = sum_i W[o,i] * X[n, i], n = (batch, dd). Persistent CTA walks
// a flat item list over all four l's; CTA keeps one M-tile parity (even GRID,
// even range bases) so the 128KB tf32 W tile reloads only on l-range entry.
// CTA tile 128 x NT, K=256 in 8 chunks of 32, B double-buffered. 16 warps as
// 4(M)x4(N). Next chunk's LDGs held in registers across the MMA block; the
// conversion+scatter STS is spread across the 4 k-step slots to smooth L1TEX
// pressure. Next tile's chunk-0 LDGs are held across the epilogue.
template <int D, int BT>
__device__ __forceinline__ void run_range(
    const float* __restrict__ x, const float* __restrict__ W,
    const float* __restrict__ bias, float* __restrict__ out,
    int off_l, int lo, int hi)
{
    constexpr int NT  = BT * D;          // multiple of 32, <= 224
    constexpr int WN  = NT / 4;          // warp n-tile
    constexpr int NF  = WN / 8;          // n8 fragments per warp
    constexpr int HB  = BT / 2;          // batches per epilogue pass
    constexpr int BSZ = NT * 128;        // bytes per B buffer
    constexpr int F4  = NT * 8;          // float4 loads per chunk

    const int cta = blockIdx.x;
    int rr = (cta - lo) % GRID; if (rr < 0) rr += GRID;
    const int start = lo + rr;
    if (start >= hi) return;             // uniform per CTA

    extern __shared__ char smem[];
    char*  As  = smem;
    char*  Bs  = smem + A_BYTES;
    float* epi = reinterpret_cast<float*>(Bs);   // epilogue reuses B region

    const int tid  = threadIdx.x;
    const int lane = tid & 31;
    const int wid  = tid >> 5;
    const int wm   = wid >> 2;
    const int wn   = wid & 3;
    const int m0   = (cta & 1) * 128;

    __syncthreads();   // previous range fully done with SMEM
    // ---- preload W tile (128 x 256) as tf32, SW128, 8 K-chunk sub-tiles ----
    for (int q = tid; q < 128 * 64; q += 512) {
        int r  = q >> 6;
        int cq = q & 63;
        float4 v = *reinterpret_cast<const float4*>(W + (size_t)(m0 + r) * 256 + cq * 4);
        uint4 u;
        u.x = f2tf32(v.x); u.y = f2tf32(v.y); u.z = f2tf32(v.z); u.w = f2tf32(v.w);
        *reinterpret_cast<uint4*>(As + (cq >> 3) * 16384 +
                                  sw128((uint32_t)(r * 128 + (cq & 7) * 16))) = u;
    }

    const int a_rowb = wm * 32 + ((lane >> 3) & 1) * 8 + (lane & 7);
    const int a_col  = ((lane >> 4) & 1) * 16;
    const int b_rowb = wn * WN + ((lane >> 4) & 1) * 8 + (lane & 7);
    const int b_col  = ((lane >> 3) & 1) * 16;
    const int b2_row = wn * WN + (NF - 1) * 8 + (lane & 7);
    const uint32_t As_u = smem_u32(smem);
    const uint32_t Bs_u = As_u + A_BYTES;

    float acc[2][NF][4];
    float4 hold[4];

    // issue LDGs for (batch-tile b0, chunk kc) into hold[]
    auto ldgB = [&](int b0, int kc) {
        const float* src0 = x + off_l + kc * (32 * D);
#pragma unroll
        for (int h = 0; h < 4; h++) {
            int q = tid + h * 512;
            hold[h] = make_float4(0.f, 0.f, 0.f, 0.f);
            if (q < F4) {
                int j  = q * 4;
                int bb = j / (32 * D);
                int jj = j - bb * (32 * D);
                if (b0 + bb < BATCH)
                    hold[h] = *reinterpret_cast<const float4*>(
                        src0 + (size_t)(bb + b0) * 4096 + jj);
            }
        }
    };
    // convert + scatter ONE quarter (h) of hold[] into B buffer `buf`
    auto stsQ = [&](int buf, int h) {
        char* dst = Bs + buf * BSZ;
        int q = tid + h * 512;
        if (q < F4) {
            int j  = q * 4;
            int bb = j / (32 * D);
            int jj = j - bb * (32 * D);
            if (D == 1) {
                // 4 consecutive i at row n=bb: one 16B store
                uint4 u;
                u.x = f2tf32(hold[h].x); u.y = f2tf32(hold[h].y);
                u.z = f2tf32(hold[h].z); u.w = f2tf32(hold[h].w);
                *reinterpret_cast<uint4*>(
                    dst + sw128((uint32_t)(bb * 128 + jj * 4))) = u;
            } else {
                float vv[4] = {hold[h].x, hold[h].y, hold[h].z, hold[h].w};
#pragma unroll
                for (int e = 0; e < 4; e++) {
                    int je = jj + e;
                    int i  = je / D;
                    int dd = je - i * D;
                    int n  = bb * D + dd;
                    *reinterpret_cast<uint32_t*>(
                        dst + sw128((uint32_t)(n * 128 + i * 4))) = f2tf32(vv[e]);
                }
            }
        }
    };

    ldgB(((start - lo) >> 1) * BT, 0);   // first tile, chunk 0

    for (int it = start; it < hi; it += GRID) {
        const int b0 = ((it - lo) >> 1) * BT;

#pragma unroll
        for (int fm = 0; fm < 2; fm++)
#pragma unroll
            for (int fn = 0; fn < NF; fn++)
#pragma unroll
                for (int e = 0; e < 4; e++) acc[fm][fn][e] = 0.0f;

        // stage chunk 0 (holds loaded pre-loop / during previous chunk 7)
#pragma unroll
        for (int h = 0; h < 4; h++) stsQ(0, h);
        __syncthreads();  // also covers W-tile publication on first iteration

#pragma unroll 1
        for (int kc = 0; kc < 8; kc++) {
            if (kc < 7) ldgB(b0, kc + 1);
            else if (it + GRID < hi) ldgB(((it + GRID - lo) >> 1) * BT, 0);
            const uint32_t Ac = As_u + kc * 16384;
            const uint32_t Bc = Bs_u + (kc & 1) * BSZ;
#pragma unroll
            for (int ks = 0; ks < 4; ks++) {
                uint32_t bfr[NF][2];
#pragma unroll
                for (int q2 = 0; q2 < NF / 2; q2++) {
                    uint32_t t[4];
                    ldsm4(t, Bc + sw128((uint32_t)((b_rowb + q2 * 16) * 128 +
                                                   ks * 32 + b_col)));
                    bfr[2 * q2][0] = t[0]; bfr[2 * q2][1] = t[1];
                    bfr[2 * q2 + 1][0] = t[2]; bfr[2 * q2 + 1][1] = t[3];
                }
                if (NF & 1) {
                    ldsm2(bfr[NF - 1], Bc + sw128((uint32_t)(b2_row * 128 +
                                                             ks * 32 + b_col)));
                }
                uint32_t af[2][4];
#pragma unroll
                for (int fm = 0; fm < 2; fm++)
                    ldsm4(af[fm], Ac + sw128((uint32_t)((a_rowb + fm * 16) * 128 +
                                                        ks * 32 + a_col)));
#pragma unroll
                for (int fm = 0; fm < 2; fm++)
#pragma unroll
                    for (int fn = 0; fn < NF; fn++)
                        mma8(acc[fm][fn], af[fm], bfr[fn]);
                // spread next-chunk staging across the 4 k-step slots
                if (kc < 7) stsQ((kc + 1) & 1, ks);
            }
            __syncthreads();
        }

        // ---- epilogue: 2 passes staged through SMEM for coalesced stores ----
#pragma unroll 1
        for (int p = 0; p < 2; p++) {
            if ((wn >> 1) == p) {
#pragma unroll
                for (int fm = 0; fm < 2; fm++) {
                    int m = wm * 32 + fm * 16 + (lane >> 2);
#pragma unroll
                    for (int fn = 0; fn < NF; fn++) {
                        const float* c = acc[fm][fn];
                        int n0  = (wn & 1) * WN + fn * 8 + (lane & 3) * 2;
                        int n1  = n0 + 1;
                        int bb0 = n0 / D, dd0 = n0 - bb0 * D;
                        int bb1 = n1 / D, dd1 = n1 - bb1 * D;
                        epi[bb0 * (128 * D) + m * D + dd0]       = c[0];
                        epi[bb1 * (128 * D) + m * D + dd1]       = c[1];
                        epi[bb0 * (128 * D) + (m + 8) * D + dd0] = c[2];
                        epi[bb1 * (128 * D) + (m + 8) * D + dd1] = c[3];
                    }
                }
            }
            __syncthreads();

            const int base_b = b0 + p * HB;
            const float4* e4 = reinterpret_cast<const float4*>(epi);
            for (int q = tid; q < HB * 32 * D; q += 512) {
                int bb = q / (32 * D);
                int r  = q - bb * (32 * D);
                int gb = base_b + bb;
                if (gb < BATCH) {
                    float4 v = e4[(size_t)bb * 32 * D + r];
                    if (D == 1) {
                        float4 bv = *reinterpret_cast<const float4*>(bias + m0 + r * 4);
                        v.x += bv.x; v.y += bv.y; v.z += bv.z; v.w += bv.w;
                    }
                    *reinterpret_cast<float4*>(
                        out + (size_t)gb * 4096 + off_l + m0 * D + r * 4) = v;
                }
            }
            __syncthreads();
        }
    }
}

// Flat item ranges (all bases even; items = 2 * n_tiles):
//  l0: D=1, BT=224, 90 tiles  -> [   0,  180)
//  l1: D=3, BT=64, 313 tiles  -> [ 180,  806)
//  l2: D=5, BT=32, 625 tiles  -> [ 806, 2056)
//  l3: D=7, BT=32, 625 tiles  -> [2056, 3306)
__global__ __launch_bounds__(512, 1)
void so3_fused(const float* __restrict__ x,
               const float* __restrict__ W0, const float* __restrict__ W1,
               const float* __restrict__ W2, const float* __restrict__ W3,
               const float* __restrict__ bias, float* __restrict__ out)
{
    run_range<1, 224>(x, W0, bias, out, 0,       0,  180);
    run_range<3,  64>(x, W1, bias, out, 256,   180,  806);
    run_range<5,  32>(x, W2, bias, out, 1024,  806, 2056);
    run_range<7,  32>(x, W3, bias, out, 2304, 2056, 3306);
}

extern "C" void kernel_launch(void* const* d_in, const int* in_sizes, int n_in,
                              void* d_out, int out_size) {
    const float* x    = (const float*)d_in[0];
    const float* W0   = (const float*)d_in[1];
    const float* W1   = (const float*)d_in[2];
    const float* W2   = (const float*)d_in[3];
    const float* W3   = (const float*)d_in[4];
    const float* bias = (const float*)d_in[5];
    float* out = (float*)d_out;

    cudaFuncSetAttribute(so3_fused, cudaFuncAttributeMaxDynamicSharedMemorySize,
                         SMEM_BYTES);
    so3_fused<<<GRID, 512, SMEM_BYTES>>>(x, W0, W1, W2, W3, bias, out);
}

// round 7
// speedup vs baseline: 1.0748x; 1.0748x over previous
#include <cuda_runtime.h>
#include <cstdint>

static constexpr int BATCH   = 20000;
static constexpr int A_BYTES = 131072;   // 8 K-chunks x 128 rows x 128B tf32 W tile
static constexpr int GRID    = 152;      // one persistent CTA per SM
static constexpr int SMEM_BYTES = A_BYTES + 3 * 224 * 128;   // 3 B buffers, max NT=224

__device__ __forceinline__ uint32_t smem_u32(const void* p) {
    uint32_t a;
    asm("{ .reg .u64 t; cvta.to.shared.u64 t, %1; cvt.u32.u64 %0, t; }" : "=r"(a) : "l"(p));
    return a;
}
__device__ __forceinline__ uint32_t f2tf32(float f) {
    uint32_t u;
    asm("cvt.rna.tf32.f32 %0, %1;" : "=r"(u) : "f"(f));
    return u;
}
__device__ __forceinline__ uint32_t sw128(uint32_t o) { return o ^ ((o >> 3) & 0x70); }

__device__ __forceinline__ void ldsm4(uint32_t* r, uint32_t a) {
    asm volatile("ldmatrix.sync.aligned.m8n8.x4.shared.b16 {%0,%1,%2,%3}, [%4];"
                 : "=r"(r[0]), "=r"(r[1]), "=r"(r[2]), "=r"(r[3]) : "r"(a));
}
__device__ __forceinline__ void ldsm2(uint32_t* r, uint32_t a) {
    asm volatile("ldmatrix.sync.aligned.m8n8.x2.shared.b16 {%0,%1}, [%2];"
                 : "=r"(r[0]), "=r"(r[1]) : "r"(a));
}
__device__ __forceinline__ void mma8(float* c, const uint32_t* a, const uint32_t* b) {
    asm volatile("mma.sync.aligned.m16n8k8.row.col.f32.tf32.tf32.f32 "
                 "{%0,%1,%2,%3}, {%4,%5,%6,%7}, {%8,%9}, {%0,%1,%2,%3};"
                 : "+f"(c[0]), "+f"(c[1]), "+f"(c[2]), "+f"(c[3])
                 : "r"(a[0]), "r"(a[1]), "r"(a[2]), "r"(a[3]), "r"(b[0]), "r"(b[1]));
}

// Per l: Y[o, n] = sum_i W[o,i] * X[n, i], n = (batch, dd). Persistent CTA walks
// a flat item list over all four l's; CTA keeps one M-tile parity (even GRID,
// even range bases) so the 128KB tf32 W tile reloads only on l-range entry.
// CTA tile 128 x NT, K=256 in 8 chunks of 32. B is TRIPLE-buffered: per chunk
// kc the body is [MMA on buf kc%3; STS buf (kc+1)%3 from hold; LDG chunk kc+2
// into hold; sync], giving each LDG a full chunk + barrier of slack before its
// STS consumes it, while MMAs start immediately after each barrier.
template <int D, int BT>
__device__ __forceinline__ void run_range(
    const float* __restrict__ x, const float* __restrict__ W,
    const float* __restrict__ bias, float* __restrict__ out,
    int off_l, int lo, int hi)
{
    constexpr int NT  = BT * D;          // multiple of 32, <= 224
    constexpr int WN  = NT / 4;          // warp n-tile
    constexpr int NF  = WN / 8;          // n8 fragments per warp
    constexpr int HB  = BT / 2;          // batches per epilogue pass
    constexpr int BSZ = NT * 128;        // bytes per B buffer
    constexpr int F4  = NT * 8;          // float4 loads per chunk

    const int cta = blockIdx.x;
    int rr = (cta - lo) % GRID; if (rr < 0) rr += GRID;
    const int start = lo + rr;
    if (start >= hi) return;             // uniform per CTA

    extern __shared__ char smem[];
    char*  As  = smem;
    char*  Bs  = smem + A_BYTES;
    float* epi = reinterpret_cast<float*>(Bs);   // epilogue reuses B region

    const int tid  = threadIdx.x;
    const int lane = tid & 31;
    const int wid  = tid >> 5;
    const int wm   = wid >> 2;
    const int wn   = wid & 3;
    const int m0   = (cta & 1) * 128;

    __syncthreads();   // previous range fully done with SMEM
    // ---- preload W tile (128 x 256) as tf32, SW128, 8 K-chunk sub-tiles ----
    for (int q = tid; q < 128 * 64; q += 512) {
        int r  = q >> 6;
        int cq = q & 63;
        float4 v = *reinterpret_cast<const float4*>(W + (size_t)(m0 + r) * 256 + cq * 4);
        uint4 u;
        u.x = f2tf32(v.x); u.y = f2tf32(v.y); u.z = f2tf32(v.z); u.w = f2tf32(v.w);
        *reinterpret_cast<uint4*>(As + (cq >> 3) * 16384 +
                                  sw128((uint32_t)(r * 128 + (cq & 7) * 16))) = u;
    }

    const int a_rowb = wm * 32 + ((lane >> 3) & 1) * 8 + (lane & 7);
    const int a_col  = ((lane >> 4) & 1) * 16;
    const int b_rowb = wn * WN + ((lane >> 4) & 1) * 8 + (lane & 7);
    const int b_col  = ((lane >> 3) & 1) * 16;
    const int b2_row = wn * WN + (NF - 1) * 8 + (lane & 7);
    const uint32_t As_u = smem_u32(smem);
    const uint32_t Bs_u = As_u + A_BYTES;

    float acc[2][NF][4];
    float4 hold[4];

    // issue LDGs for (batch-tile b0, chunk kc) into hold[]
    auto ldgB = [&](int b0, int kc) {
        const float* src0 = x + off_l + kc * (32 * D);
#pragma unroll
        for (int h = 0; h < 4; h++) {
            int q = tid + h * 512;
            hold[h] = make_float4(0.f, 0.f, 0.f, 0.f);
            if (q < F4) {
                int j  = q * 4;
                int bb = j / (32 * D);
                int jj = j - bb * (32 * D);
                if (b0 + bb < BATCH)
                    hold[h] = *reinterpret_cast<const float4*>(
                        src0 + (size_t)(bb + b0) * 4096 + jj);
            }
        }
    };
    // convert + scatter hold[] into B buffer `buf` (lumped, all quarters)
    auto stsB = [&](int buf) {
        char* dst = Bs + buf * BSZ;
#pragma unroll
        for (int h = 0; h < 4; h++) {
            int q = tid + h * 512;
            if (q < F4) {
                int j  = q * 4;
                int bb = j / (32 * D);
                int jj = j - bb * (32 * D);
                if (D == 1) {
                    // 4 consecutive i in row n=bb: one 16B store
                    uint4 u;
                    u.x = f2tf32(hold[h].x); u.y = f2tf32(hold[h].y);
                    u.z = f2tf32(hold[h].z); u.w = f2tf32(hold[h].w);
                    *reinterpret_cast<uint4*>(
                        dst + sw128((uint32_t)(bb * 128 + jj * 4))) = u;
                } else {
                    float vv[4] = {hold[h].x, hold[h].y, hold[h].z, hold[h].w};
#pragma unroll
                    for (int e = 0; e < 4; e++) {
                        int je = jj + e;
                        int i  = je / D;
                        int dd = je - i * D;
                        int n  = bb * D + dd;
                        *reinterpret_cast<uint32_t*>(
                            dst + sw128((uint32_t)(n * 128 + i * 4))) = f2tf32(vv[e]);
                    }
                }
            }
        }
    };

    ldgB(((start - lo) >> 1) * BT, 0);   // first tile, chunk 0 -> hold

    for (int it = start; it < hi; it += GRID) {
        const int b0 = ((it - lo) >> 1) * BT;

#pragma unroll
        for (int fm = 0; fm < 2; fm++)
#pragma unroll
            for (int fn = 0; fn < NF; fn++)
#pragma unroll
                for (int e = 0; e < 4; e++) acc[fm][fn][e] = 0.0f;

        // prologue: stage chunk 0 (held since previous tile / pre-loop),
        // then issue chunk 1 LDGs (consumed at end of chunk 0's MMA).
        stsB(0);
        ldgB(b0, 1);
        __syncthreads();  // also covers W-tile publication on first iteration

#pragma unroll 1
        for (int kc = 0; kc < 8; kc++) {
            const uint32_t Ac = As_u + kc * 16384;
            const uint32_t Bc = Bs_u + (kc % 3) * BSZ;
#pragma unroll
            for (int ks = 0; ks < 4; ks++) {
                uint32_t af[2][4];
#pragma unroll
                for (int fm = 0; fm < 2; fm++)
                    ldsm4(af[fm], Ac + sw128((uint32_t)((a_rowb + fm * 16) * 128 +
                                                        ks * 32 + a_col)));
                uint32_t bfr[NF][2];
#pragma unroll
                for (int q2 = 0; q2 < NF / 2; q2++) {
                    uint32_t t[4];
                    ldsm4(t, Bc + sw128((uint32_t)((b_rowb + q2 * 16) * 128 +
                                                   ks * 32 + b_col)));
                    bfr[2 * q2][0] = t[0]; bfr[2 * q2][1] = t[1];
                    bfr[2 * q2 + 1][0] = t[2]; bfr[2 * q2 + 1][1] = t[3];
                }
                if (NF & 1) {
                    ldsm2(bfr[NF - 1], Bc + sw128((uint32_t)(b2_row * 128 +
                                                             ks * 32 + b_col)));
                }
#pragma unroll
                for (int fm = 0; fm < 2; fm++)
#pragma unroll
                    for (int fn = 0; fn < NF; fn++)
                        mma8(acc[fm][fn], af[fm], bfr[fn]);
            }
            // stage chunk kc+1 (its LDGs have had a full chunk of slack),
            // then issue LDGs for chunk kc+2 (or next tile's chunk 0).
            if (kc <= 6) {
                stsB((kc + 1) % 3);
                if (kc <= 5) ldgB(b0, kc + 2);
                else if (it + GRID < hi) ldgB(((it + GRID - lo) >> 1) * BT, 0);
            }
            __syncthreads();
        }

        // ---- epilogue: 2 passes staged through SMEM for coalesced stores ----
#pragma unroll 1
        for (int p = 0; p < 2; p++) {
            if ((wn >> 1) == p) {
#pragma unroll
                for (int fm = 0; fm < 2; fm++) {
                    int m = wm * 32 + fm * 16 + (lane >> 2);
#pragma unroll
                    for (int fn = 0; fn < NF; fn++) {
                        const float* c = acc[fm][fn];
                        int n0  = (wn & 1) * WN + fn * 8 + (lane & 3) * 2;
                        int n1  = n0 + 1;
                        int bb0 = n0 / D, dd0 = n0 - bb0 * D;
                        int bb1 = n1 / D, dd1 = n1 - bb1 * D;
                        epi[bb0 * (128 * D) + m * D + dd0]       = c[0];
                        epi[bb1 * (128 * D) + m * D + dd1]       = c[1];
                        epi[bb0 * (128 * D) + (m + 8) * D + dd0] = c[2];
                        epi[bb1 * (128 * D) + (m + 8) * D + dd1] = c[3];
                    }
                }
            }
            __syncthreads();

            const int base_b = b0 + p * HB;
            const float4* e4 = reinterpret_cast<const float4*>(epi);
            for (int q = tid; q < HB * 32 * D; q += 512) {
                int bb = q / (32 * D);
                int r  = q - bb * (32 * D);
                int gb = base_b + bb;
                if (gb < BATCH) {
                    float4 v = e4[(size_t)bb * 32 * D + r];
                    if (D == 1) {
                        float4 bv = *reinterpret_cast<const float4*>(bias + m0 + r * 4);
                        v.x += bv.x; v.y += bv.y; v.z += bv.z; v.w += bv.w;
                    }
                    *reinterpret_cast<float4*>(
                        out + (size_t)gb * 4096 + off_l + m0 * D + r * 4) = v;
                }
            }
            __syncthreads();
        }
    }
}

// Flat item ranges (all bases even; items = 2 * n_tiles):
//  l0: D=1, BT=224, 90 tiles  -> [   0,  180)
//  l1: D=3, BT=64, 313 tiles  -> [ 180,  806)
//  l2: D=5, BT=32, 625 tiles  -> [ 806, 2056)
//  l3: D=7, BT=32, 625 tiles  -> [2056, 3306)
__global__ __launch_bounds__(512, 1)
void so3_fused(const float* __restrict__ x,
               const float* __restrict__ W0, const float* __restrict__ W1,
               const float* __restrict__ W2, const float* __restrict__ W3,
               const float* __restrict__ bias, float* __restrict__ out)
{
    run_range<1, 224>(x, W0, bias, out, 0,       0,  180);
    run_range<3,  64>(x, W1, bias, out, 256,   180,  806);
    run_range<5,  32>(x, W2, bias, out, 1024,  806, 2056);
    run_range<7,  32>(x, W3, bias, out, 2304, 2056, 3306);
}

extern "C" void kernel_launch(void* const* d_in, const int* in_sizes, int n_in,
                              void* d_out, int out_size) {
    const float* x    = (const float*)d_in[0];
    const float* W0   = (const float*)d_in[1];
    const float* W1   = (const float*)d_in[2];
    const float* W2   = (const float*)d_in[3];
    const float* W3   = (const float*)d_in[4];
    const float* bias = (const float*)d_in[5];
    float* out = (float*)d_out;

    cudaFuncSetAttribute(so3_fused, cudaFuncAttributeMaxDynamicSharedMemorySize,
                         SMEM_BYTES);
    so3_fused<<<GRID, 512, SMEM_BYTES>>>(x, W0, W1, W2, W3, bias, out);
}

// round 8
// speedup vs baseline: 1.1964x; 1.1132x over previous
#include <cuda_runtime.h>
#include <cstdint>

static constexpr int BATCH   = 20000;
static constexpr int A_BYTES = 131072;   // 8 K-chunks x 128 rows x 128B tf32 W tile
static constexpr int GRID    = 152;      // one persistent CTA per SM
static constexpr int SMEM_BYTES = A_BYTES + 2 * 224 * 128;   // max NT = 224

__device__ __forceinline__ uint32_t smem_u32(const void* p) {
    uint32_t a;
    asm("{ .reg .u64 t; cvta.to.shared.u64 t, %1; cvt.u32.u64 %0, t; }" : "=r"(a) : "l"(p));
    return a;
}
__device__ __forceinline__ uint32_t f2tf32(float f) {
    uint32_t u;
    asm("cvt.rna.tf32.f32 %0, %1;" : "=r"(u) : "f"(f));
    return u;
}
__device__ __forceinline__ uint32_t sw128(uint32_t o) { return o ^ ((o >> 3) & 0x70); }

__device__ __forceinline__ void ldsm4(uint32_t* r, uint32_t a) {
    asm volatile("ldmatrix.sync.aligned.m8n8.x4.shared.b16 {%0,%1,%2,%3}, [%4];"
                 : "=r"(r[0]), "=r"(r[1]), "=r"(r[2]), "=r"(r[3]) : "r"(a));
}
__device__ __forceinline__ void ldsm2(uint32_t* r, uint32_t a) {
    asm volatile("ldmatrix.sync.aligned.m8n8.x2.shared.b16 {%0,%1}, [%2];"
                 : "=r"(r[0]), "=r"(r[1]) : "r"(a));
}
__device__ __forceinline__ void mma8(float* c, const uint32_t* a, const uint32_t* b) {
    asm volatile("mma.sync.aligned.m16n8k8.row.col.f32.tf32.tf32.f32 "
                 "{%0,%1,%2,%3}, {%4,%5,%6,%7}, {%8,%9}, {%0,%1,%2,%3};"
                 : "+f"(c[0]), "+f"(c[1]), "+f"(c[2]), "+f"(c[3])
                 : "r"(a[0]), "r"(a[1]), "r"(a[2]), "r"(a[3]), "r"(b[0]), "r"(b[1]));
}

// Per l: Y[o, n] = sum_i W[o,i] * X[n, i], n = (batch, dd). Persistent CTA walks
// a flat item list over all four l's; CTA keeps one M-tile parity (even GRID,
// even range bases) so the 128KB tf32 W tile reloads only on l-range entry.
// CTA tile 128 x NT, K=256 in 8 chunks of 32, B double-buffered (R4 layout).
// 16 warps as 4(M)x4(N). Inside each chunk the 4 k-steps are SOFTWARE
// PIPELINED: A/B fragments for ks+1 are ldsm'd at the top of ks's MMA block,
// so no MMA waits on a just-issued LDSM.
template <int D, int BT>
__device__ __forceinline__ void run_range(
    const float* __restrict__ x, const float* __restrict__ W,
    const float* __restrict__ bias, float* __restrict__ out,
    int off_l, int lo, int hi)
{
    constexpr int NT  = BT * D;          // multiple of 32, <= 224
    constexpr int WN  = NT / 4;          // warp n-tile
    constexpr int NF  = WN / 8;          // n8 fragments per warp
    constexpr int HB  = BT / 2;          // batches per epilogue pass
    constexpr int BSZ = NT * 128;        // bytes per B buffer
    constexpr int F4  = NT * 8;          // float4 loads per chunk

    const int cta = blockIdx.x;
    int rr = (cta - lo) % GRID; if (rr < 0) rr += GRID;
    const int start = lo + rr;
    if (start >= hi) return;             // uniform per CTA

    extern __shared__ char smem[];
    char*  As  = smem;
    char*  Bs  = smem + A_BYTES;
    float* epi = reinterpret_cast<float*>(Bs);   // epilogue reuses B region

    const int tid  = threadIdx.x;
    const int lane = tid & 31;
    const int wid  = tid >> 5;
    const int wm   = wid >> 2;
    const int wn   = wid & 3;
    const int m0   = (cta & 1) * 128;

    __syncthreads();   // previous range fully done with SMEM
    // ---- preload W tile (128 x 256) as tf32, SW128, 8 K-chunk sub-tiles ----
    for (int q = tid; q < 128 * 64; q += 512) {
        int r  = q >> 6;
        int cq = q & 63;
        float4 v = *reinterpret_cast<const float4*>(W + (size_t)(m0 + r) * 256 + cq * 4);
        uint4 u;
        u.x = f2tf32(v.x); u.y = f2tf32(v.y); u.z = f2tf32(v.z); u.w = f2tf32(v.w);
        *reinterpret_cast<uint4*>(As + (cq >> 3) * 16384 +
                                  sw128((uint32_t)(r * 128 + (cq & 7) * 16))) = u;
    }

    const int a_rowb = wm * 32 + ((lane >> 3) & 1) * 8 + (lane & 7);
    const int a_col  = ((lane >> 4) & 1) * 16;
    const int b_rowb = wn * WN + ((lane >> 4) & 1) * 8 + (lane & 7);
    const int b_col  = ((lane >> 3) & 1) * 16;
    const int b2_row = wn * WN + (NF - 1) * 8 + (lane & 7);
    const uint32_t As_u = smem_u32(smem);
    const uint32_t Bs_u = As_u + A_BYTES;

    float acc[2][NF][4];
    float4 hold[4];
    uint32_t af[2][2][4];        // [bank][fm][regs]
    uint32_t bfr[2][NF][2];      // [bank][fn][regs]

    // fragment loaders for k-step ks of chunk at (Ac, Bc)
    auto ldA = [&](int bank, uint32_t Ac, int ks) {
#pragma unroll
        for (int fm = 0; fm < 2; fm++)
            ldsm4(af[bank][fm], Ac + sw128((uint32_t)((a_rowb + fm * 16) * 128 +
                                                      ks * 32 + a_col)));
    };
    auto ldB = [&](int bank, uint32_t Bc, int ks) {
#pragma unroll
        for (int q2 = 0; q2 < NF / 2; q2++) {
            uint32_t t[4];
            ldsm4(t, Bc + sw128((uint32_t)((b_rowb + q2 * 16) * 128 +
                                           ks * 32 + b_col)));
            bfr[bank][2 * q2][0] = t[0]; bfr[bank][2 * q2][1] = t[1];
            bfr[bank][2 * q2 + 1][0] = t[2]; bfr[bank][2 * q2 + 1][1] = t[3];
        }
        if (NF & 1)
            ldsm2(bfr[bank][NF - 1], Bc + sw128((uint32_t)(b2_row * 128 +
                                                           ks * 32 + b_col)));
    };

    // issue LDGs for (batch-tile b0, chunk kc) into hold[]
    auto ldgB = [&](int b0, int kc) {
        const float* src0 = x + off_l + kc * (32 * D);
#pragma unroll
        for (int h = 0; h < 4; h++) {
            int q = tid + h * 512;
            hold[h] = make_float4(0.f, 0.f, 0.f, 0.f);
            if (q < F4) {
                int j  = q * 4;
                int bb = j / (32 * D);
                int jj = j - bb * (32 * D);
                if (b0 + bb < BATCH)
                    hold[h] = *reinterpret_cast<const float4*>(
                        src0 + (size_t)(bb + b0) * 4096 + jj);
            }
        }
    };
    // convert + scatter hold[] into B buffer `buf`
    auto stsB = [&](int buf) {
        char* dst = Bs + buf * BSZ;
#pragma unroll
        for (int h = 0; h < 4; h++) {
            int q = tid + h * 512;
            if (q < F4) {
                int j  = q * 4;
                int bb = j / (32 * D);
                int jj = j - bb * (32 * D);
                if (D == 1) {
                    uint4 u;
                    u.x = f2tf32(hold[h].x); u.y = f2tf32(hold[h].y);
                    u.z = f2tf32(hold[h].z); u.w = f2tf32(hold[h].w);
                    *reinterpret_cast<uint4*>(
                        dst + sw128((uint32_t)(bb * 128 + jj * 4))) = u;
                } else {
                    float vv[4] = {hold[h].x, hold[h].y, hold[h].z, hold[h].w};
#pragma unroll
                    for (int e = 0; e < 4; e++) {
                        int je = jj + e;
                        int i  = je / D;
                        int dd = je - i * D;
                        int n  = bb * D + dd;
                        *reinterpret_cast<uint32_t*>(
                            dst + sw128((uint32_t)(n * 128 + i * 4))) = f2tf32(vv[e]);
                    }
                }
            }
        }
    };

    ldgB(((start - lo) >> 1) * BT, 0);   // first tile, chunk 0

    for (int it = start; it < hi; it += GRID) {
        const int b0 = ((it - lo) >> 1) * BT;

#pragma unroll
        for (int fm = 0; fm < 2; fm++)
#pragma unroll
            for (int fn = 0; fn < NF; fn++)
#pragma unroll
                for (int e = 0; e < 4; e++) acc[fm][fn][e] = 0.0f;

        stsB(0);          // chunk 0 (held since previous tile / pre-loop)
        __syncthreads();  // also covers W-tile publication on first iteration

#pragma unroll 1
        for (int kc = 0; kc < 8; kc++) {
            if (kc < 7) ldgB(b0, kc + 1);
            else if (it + GRID < hi) ldgB(((it + GRID - lo) >> 1) * BT, 0);
            const uint32_t Ac = As_u + kc * 16384;
            const uint32_t Bc = Bs_u + (kc & 1) * BSZ;
            // prime k-step 0 fragments
            ldB(0, Bc, 0);
            ldA(0, Ac, 0);
#pragma unroll
            for (int ks = 0; ks < 4; ks++) {
                const int cur = ks & 1;
                if (ks < 3) {            // prefetch ks+1 before consuming ks
                    ldB(cur ^ 1, Bc, ks + 1);
                    ldA(cur ^ 1, Ac, ks + 1);
                }
#pragma unroll
                for (int fm = 0; fm < 2; fm++)
#pragma unroll
                    for (int fn = 0; fn < NF; fn++)
                        mma8(acc[fm][fn], af[cur][fm], bfr[cur][fn]);
            }
            if (kc < 7) stsB((kc + 1) & 1);
            __syncthreads();
        }

        // ---- epilogue: 2 passes staged through SMEM for coalesced stores ----
#pragma unroll 1
        for (int p = 0; p < 2; p++) {
            if ((wn >> 1) == p) {
#pragma unroll
                for (int fm = 0; fm < 2; fm++) {
                    int m = wm * 32 + fm * 16 + (lane >> 2);
#pragma unroll
                    for (int fn = 0; fn < NF; fn++) {
                        const float* c = acc[fm][fn];
                        int n0  = (wn & 1) * WN + fn * 8 + (lane & 3) * 2;
                        int n1  = n0 + 1;
                        int bb0 = n0 / D, dd0 = n0 - bb0 * D;
                        int bb1 = n1 / D, dd1 = n1 - bb1 * D;
                        epi[bb0 * (128 * D) + m * D + dd0]       = c[0];
                        epi[bb1 * (128 * D) + m * D + dd1]       = c[1];
                        epi[bb0 * (128 * D) + (m + 8) * D + dd0] = c[2];
                        epi[bb1 * (128 * D) + (m + 8) * D + dd1] = c[3];
                    }
                }
            }
            __syncthreads();

            const int base_b = b0 + p * HB;
            const float4* e4 = reinterpret_cast<const float4*>(epi);
            for (int q = tid; q < HB * 32 * D; q += 512) {
                int bb = q / (32 * D);
                int r  = q - bb * (32 * D);
                int gb = base_b + bb;
                if (gb < BATCH) {
                    float4 v = e4[(size_t)bb * 32 * D + r];
                    if (D == 1) {
                        float4 bv = *reinterpret_cast<const float4*>(bias + m0 + r * 4);
                        v.x += bv.x; v.y += bv.y; v.z += bv.z; v.w += bv.w;
                    }
                    *reinterpret_cast<float4*>(
                        out + (size_t)gb * 4096 + off_l + m0 * D + r * 4) = v;
                }
            }
            __syncthreads();
        }
    }
}

// Flat item ranges (all bases even; items = 2 * n_tiles):
//  l0: D=1, BT=224, 90 tiles  -> [   0,  180)
//  l1: D=3, BT=64, 313 tiles  -> [ 180,  806)
//  l2: D=5, BT=32, 625 tiles  -> [ 806, 2056)
//  l3: D=7, BT=32, 625 tiles  -> [2056, 3306)
__global__ __launch_bounds__(512, 1)
void so3_fused(const float* __restrict__ x,
               const float* __restrict__ W0, const float* __restrict__ W1,
               const float* __restrict__ W2, const float* __restrict__ W3,
               const float* __restrict__ bias, float* __restrict__ out)
{
    run_range<1, 224>(x, W0, bias, out, 0,       0,  180);
    run_range<3,  64>(x, W1, bias, out, 256,   180,  806);
    run_range<5,  32>(x, W2, bias, out, 1024,  806, 2056);
    run_range<7,  32>(x, W3, bias, out, 2304, 2056, 3306);
}

extern "C" void kernel_launch(void* const* d_in, const int* in_sizes, int n_in,
                              void* d_out, int out_size) {
    const float* x    = (const float*)d_in[0];
    const float* W0   = (const float*)d_in[1];
    const float* W1   = (const float*)d_in[2];
    const float* W2   = (const float*)d_in[3];
    const float* W3   = (const float*)d_in[4];
    const float* bias = (const float*)d_in[5];
    float* out = (float*)d_out;

    cudaFuncSetAttribute(so3_fused, cudaFuncAttributeMaxDynamicSharedMemorySize,
                         SMEM_BYTES);
    so3_fused<<<GRID, 512, SMEM_BYTES>>>(x, W0, W1, W2, W3, bias, out);
}

// round 9
// speedup vs baseline: 1.5119x; 1.2637x over previous
#include <cuda_runtime.h>
#include <cuda_fp16.h>
#include <cstdint>

static constexpr int BATCH   = 20000;
static constexpr int A_BYTES = 65536;    // 8 K-chunks x 128 rows x 64B fp16 W tile
static constexpr int GRID    = 152;      // one persistent CTA per SM
// A + 2 B buffers (max NT=224: 2*14KB) + epilogue staging (max 57KB)
static constexpr int SMEM_BYTES = A_BYTES + 2 * 224 * 64 + 224 * 256;  // 151552

__device__ __forceinline__ uint32_t smem_u32(const void* p) {
    uint32_t a;
    asm("{ .reg .u64 t; cvta.to.shared.u64 t, %1; cvt.u32.u64 %0, t; }" : "=r"(a) : "l"(p));
    return a;
}
__device__ __forceinline__ uint32_t pack_h2(float lo, float hi) {
    __half2 h = __floats2half2_rn(lo, hi);   // .x = lo (low 16 bits)
    return *reinterpret_cast<uint32_t*>(&h);
}
__device__ __forceinline__ uint32_t sw64(uint32_t o) { return o ^ ((o >> 3) & 0x30); }

__device__ __forceinline__ void ldsm4(uint32_t* r, uint32_t a) {
    asm volatile("ldmatrix.sync.aligned.m8n8.x4.shared.b16 {%0,%1,%2,%3}, [%4];"
                 : "=r"(r[0]), "=r"(r[1]), "=r"(r[2]), "=r"(r[3]) : "r"(a));
}
__device__ __forceinline__ void ldsm2(uint32_t* r, uint32_t a) {
    asm volatile("ldmatrix.sync.aligned.m8n8.x2.shared.b16 {%0,%1}, [%2];"
                 : "=r"(r[0]), "=r"(r[1]) : "r"(a));
}
__device__ __forceinline__ void mma16(float* c, const uint32_t* a, const uint32_t* b) {
    asm volatile("mma.sync.aligned.m16n8k16.row.col.f32.f16.f16.f32 "
                 "{%0,%1,%2,%3}, {%4,%5,%6,%7}, {%8,%9}, {%0,%1,%2,%3};"
                 : "+f"(c[0]), "+f"(c[1]), "+f"(c[2]), "+f"(c[3])
                 : "r"(a[0]), "r"(a[1]), "r"(a[2]), "r"(a[3]), "r"(b[0]), "r"(b[1]));
}

// Per l: Y[o, n] = sum_i W[o,i] * X[n, i], n = (batch, dd). Persistent CTA walks
// a flat item list over all four l's; CTA keeps one M-tile parity (even GRID,
// even range bases) so the fp16 W tile (64KB) reloads only on l-range entry.
// CTA tile 128 x NT, K=256 in 8 chunks of 32, fp16 operands (f32 accum), rows
// of 64B with SW64 swizzle. B double-buffered; R4 dataflow: LDG chunk kc+1 at
// top of chunk kc, STS at its end. 16 warps as 4(M)x4(N); 2 K16 steps/chunk.
template <int D, int BT>
__device__ __forceinline__ void run_range(
    const float* __restrict__ x, const float* __restrict__ W,
    const float* __restrict__ bias, float* __restrict__ out,
    int off_l, int lo, int hi)
{
    constexpr int NT  = BT * D;          // multiple of 32, <= 224
    constexpr int WN  = NT / 4;          // warp n-tile
    constexpr int NF  = WN / 8;          // n8 fragments per warp
    constexpr int HB  = BT / 2;          // batches per epilogue pass
    constexpr int BSZ = NT * 64;         // bytes per B buffer (fp16 rows)
    constexpr int F4  = NT * 8;          // float4 loads per chunk (32*D floats/batch)

    const int cta = blockIdx.x;
    int rr = (cta - lo) % GRID; if (rr < 0) rr += GRID;
    const int start = lo + rr;
    if (start >= hi) return;             // uniform per CTA

    extern __shared__ char smem[];
    char*  As  = smem;
    char*  Bs  = smem + A_BYTES;
    float* epi = reinterpret_cast<float*>(smem + A_BYTES + 2 * BSZ);

    const int tid  = threadIdx.x;
    const int lane = tid & 31;
    const int wid  = tid >> 5;
    const int wm   = wid >> 2;
    const int wn   = wid & 3;
    const int m0   = (cta & 1) * 128;

    __syncthreads();   // previous range fully done with SMEM
    // ---- preload W tile (128 x 256) as fp16, SW64, 8 K-chunk sub-tiles ----
    for (int q = tid; q < 128 * 64; q += 512) {
        int r  = q >> 6;
        int cq = q & 63;
        float4 v = *reinterpret_cast<const float4*>(W + (size_t)(m0 + r) * 256 + cq * 4);
        uint2 u;
        u.x = pack_h2(v.x, v.y);
        u.y = pack_h2(v.z, v.w);
        *reinterpret_cast<uint2*>(As + (cq >> 3) * 8192 +
                                  sw64((uint32_t)(r * 64 + (cq & 7) * 8))) = u;
    }

    // ldmatrix lane address components (16-row x4: lanes 0-7 rows, 8-15 rows+8,
    // 16-31 same rows at +16B column)
    const int a_rowb = wm * 32 + ((lane >> 3) & 1) * 8 + (lane & 7);
    const int a_col  = ((lane >> 4) & 1) * 16;
    const int b_rowb = wn * WN + ((lane >> 4) & 1) * 8 + (lane & 7);
    const int b_col  = ((lane >> 3) & 1) * 16;
    const int b2_row = wn * WN + (NF - 1) * 8 + (lane & 7);
    const uint32_t As_u = smem_u32(smem);
    const uint32_t Bs_u = As_u + A_BYTES;

    float acc[2][NF][4];
    float4 hold[4];

    // issue LDGs for (batch-tile b0, chunk kc) into hold[]
    auto ldgB = [&](int b0, int kc) {
        const float* src0 = x + off_l + kc * (32 * D);
#pragma unroll
        for (int h = 0; h < 4; h++) {
            int q = tid + h * 512;
            hold[h] = make_float4(0.f, 0.f, 0.f, 0.f);
            if (q < F4) {
                int j  = q * 4;
                int bb = j / (32 * D);
                int jj = j - bb * (32 * D);
                if (b0 + bb < BATCH)
                    hold[h] = *reinterpret_cast<const float4*>(
                        src0 + (size_t)(bb + b0) * 4096 + jj);
            }
        }
    };
    // convert + scatter hold[] into B buffer `buf` (fp16, SW64 rows of 64B)
    auto stsB = [&](int buf) {
        char* dst = Bs + buf * BSZ;
#pragma unroll
        for (int h = 0; h < 4; h++) {
            int q = tid + h * 512;
            if (q < F4) {
                int j  = q * 4;
                int bb = j / (32 * D);
                int jj = j - bb * (32 * D);
                if (D == 1) {
                    // 4 consecutive k in row n=bb: one 8B store
                    uint2 u;
                    u.x = pack_h2(hold[h].x, hold[h].y);
                    u.y = pack_h2(hold[h].z, hold[h].w);
                    *reinterpret_cast<uint2*>(
                        dst + sw64((uint32_t)(bb * 64 + jj * 2))) = u;
                } else {
                    float vv[4] = {hold[h].x, hold[h].y, hold[h].z, hold[h].w};
#pragma unroll
                    for (int e = 0; e < 4; e++) {
                        int je = jj + e;
                        int i  = je / D;
                        int dd = je - i * D;
                        int n  = bb * D + dd;
                        *reinterpret_cast<__half*>(
                            dst + sw64((uint32_t)(n * 64 + i * 2))) =
                            __float2half_rn(vv[e]);
                    }
                }
            }
        }
    };

    ldgB(((start - lo) >> 1) * BT, 0);   // first tile, chunk 0

    for (int it = start; it < hi; it += GRID) {
        const int b0 = ((it - lo) >> 1) * BT;

#pragma unroll
        for (int fm = 0; fm < 2; fm++)
#pragma unroll
            for (int fn = 0; fn < NF; fn++)
#pragma unroll
                for (int e = 0; e < 4; e++) acc[fm][fn][e] = 0.0f;

        stsB(0);          // chunk 0 (held since previous tile / pre-loop)
        __syncthreads();  // also covers W-tile publication on first iteration

#pragma unroll 1
        for (int kc = 0; kc < 8; kc++) {
            if (kc < 7) ldgB(b0, kc + 1);
            else if (it + GRID < hi) ldgB(((it + GRID - lo) >> 1) * BT, 0);
            const uint32_t Ac = As_u + kc * 8192;
            const uint32_t Bc = Bs_u + (kc & 1) * BSZ;
#pragma unroll
            for (int ks = 0; ks < 2; ks++) {          // 2 K16 steps per chunk
                uint32_t bfr[NF][2];
#pragma unroll
                for (int q2 = 0; q2 < NF / 2; q2++) {
                    uint32_t t[4];
                    ldsm4(t, Bc + sw64((uint32_t)((b_rowb + q2 * 16) * 64 +
                                                  ks * 32 + b_col)));
                    bfr[2 * q2][0] = t[0]; bfr[2 * q2][1] = t[1];
                    bfr[2 * q2 + 1][0] = t[2]; bfr[2 * q2 + 1][1] = t[3];
                }
                if (NF & 1) {
                    ldsm2(bfr[NF - 1], Bc + sw64((uint32_t)(b2_row * 64 +
                                                            ks * 32 + b_col)));
                }
                uint32_t af[2][4];
#pragma unroll
                for (int fm = 0; fm < 2; fm++)
                    ldsm4(af[fm], Ac + sw64((uint32_t)((a_rowb + fm * 16) * 64 +
                                                       ks * 32 + a_col)));
#pragma unroll
                for (int fm = 0; fm < 2; fm++)
#pragma unroll
                    for (int fn = 0; fn < NF; fn++)
                        mma16(acc[fm][fn], af[fm], bfr[fn]);
            }
            if (kc < 7) stsB((kc + 1) & 1);
            __syncthreads();
        }

        // ---- epilogue: 2 passes staged through dedicated SMEM region ----
#pragma unroll 1
        for (int p = 0; p < 2; p++) {
            if ((wn >> 1) == p) {
#pragma unroll
                for (int fm = 0; fm < 2; fm++) {
                    int m = wm * 32 + fm * 16 + (lane >> 2);
#pragma unroll
                    for (int fn = 0; fn < NF; fn++) {
                        const float* c = acc[fm][fn];
                        int n0  = (wn & 1) * WN + fn * 8 + (lane & 3) * 2;
                        int n1  = n0 + 1;
                        int bb0 = n0 / D, dd0 = n0 - bb0 * D;
                        int bb1 = n1 / D, dd1 = n1 - bb1 * D;
                        epi[bb0 * (128 * D) + m * D + dd0]       = c[0];
                        epi[bb1 * (128 * D) + m * D + dd1]       = c[1];
                        epi[bb0 * (128 * D) + (m + 8) * D + dd0] = c[2];
                        epi[bb1 * (128 * D) + (m + 8) * D + dd1] = c[3];
                    }
                }
            }
            __syncthreads();

            const int base_b = b0 + p * HB;
            const float4* e4 = reinterpret_cast<const float4*>(epi);
            for (int q = tid; q < HB * 32 * D; q += 512) {
                int bb = q / (32 * D);
                int r  = q - bb * (32 * D);
                int gb = base_b + bb;
                if (gb < BATCH) {
                    float4 v = e4[(size_t)bb * 32 * D + r];
                    if (D == 1) {
                        float4 bv = *reinterpret_cast<const float4*>(bias + m0 + r * 4);
                        v.x += bv.x; v.y += bv.y; v.z += bv.z; v.w += bv.w;
                    }
                    *reinterpret_cast<float4*>(
                        out + (size_t)gb * 4096 + off_l + m0 * D + r * 4) = v;
                }
            }
            __syncthreads();
        }
    }
}

// Flat item ranges (all bases even; items = 2 * n_tiles):
//  l0: D=1, BT=224, 90 tiles  -> [   0,  180)
//  l1: D=3, BT=64, 313 tiles  -> [ 180,  806)
//  l2: D=5, BT=32, 625 tiles  -> [ 806, 2056)
//  l3: D=7, BT=32, 625 tiles  -> [2056, 3306)
__global__ __launch_bounds__(512, 1)
void so3_fused(const float* __restrict__ x,
               const float* __restrict__ W0, const float* __restrict__ W1,
               const float* __restrict__ W2, const float* __restrict__ W3,
               const float* __restrict__ bias, float* __restrict__ out)
{
    run_range<1, 224>(x, W0, bias, out, 0,       0,  180);
    run_range<3,  64>(x, W1, bias, out, 256,   180,  806);
    run_range<5,  32>(x, W2, bias, out, 1024,  806, 2056);
    run_range<7,  32>(x, W3, bias, out, 2304, 2056, 3306);
}

extern "C" void kernel_launch(void* const* d_in, const int* in_sizes, int n_in,
                              void* d_out, int out_size) {
    const float* x    = (const float*)d_in[0];
    const float* W0   = (const float*)d_in[1];
    const float* W1   = (const float*)d_in[2];
    const float* W2   = (const float*)d_in[3];
    const float* W3   = (const float*)d_in[4];
    const float* bias = (const float*)d_in[5];
    float* out = (float*)d_out;

    cudaFuncSetAttribute(so3_fused, cudaFuncAttributeMaxDynamicSharedMemorySize,
                         SMEM_BYTES);
    so3_fused<<<GRID, 512, SMEM_BYTES>>>(x, W0, W1, W2, W3, bias, out);
}